// round 10
// baseline (speedup 1.0000x reference)
#include <cuda_runtime.h>
#include <cuda_bf16.h>
#include <stdint.h>
#include <math.h>

#define NTOK 16384
#define Dm   1024
#define Hm   4096
#define Em   8
#define LSm  1824
#define MTILE 128
#define MAXROWS 33792        // 264 * 128
#define MAXTILES 264
#define BK 32                // bf16 K per chunk
#define ROWB 80              // 64B data + 16B pad per smem row
#define PLANE_BYTES (128 * ROWB)           // 10240
#define SLOT_BYTES  (4 * PLANE_BYTES)      // 40960 static smem

// ---------------- device scratch (~554 MB total, proven safe) ----------------
__device__ int   g_cnt[Em];
__device__ int   g_off[Em + 1];
__device__ int   g_cursor[Em];
__device__ int   g_top_e[NTOK * 2];
__device__ float g_top_g[NTOK * 2];
__device__ int   g_row_tok[MAXROWS];
__device__ float g_row_gate[MAXROWS];
__device__ float g_h[(size_t)MAXROWS * Hm];   // fp32 hidden, 553 MB

#define MMA16816(d, a, b) \
    asm volatile("mma.sync.aligned.m16n8k16.row.col.f32.bf16.bf16.f32 " \
        "{%0,%1,%2,%3}, {%4,%5,%6,%7}, {%8,%9}, {%0,%1,%2,%3};" \
        : "+f"((d)[0]), "+f"((d)[1]), "+f"((d)[2]), "+f"((d)[3]) \
        : "r"((a)[0]), "r"((a)[1]), "r"((a)[2]), "r"((a)[3]), \
          "r"((b)[0]), "r"((b)[1]))

// packed split: one CVT for hi pair, exact reconstruct via <<16, one CVT for lo
__device__ __forceinline__ void split2(float a, float b,
                                       uint32_t& hi, uint32_t& lo) {
    __nv_bfloat162 H = __float22bfloat162_rn(make_float2(a, b));
    uint32_t hbits = *(uint32_t*)&H;
    float ha_f = __uint_as_float(hbits << 16);            // exact bf16->f32
    float hb_f = __uint_as_float(hbits & 0xFFFF0000u);
    __nv_bfloat162 L = __float22bfloat162_rn(make_float2(a - ha_f, b - hb_f));
    hi = hbits;
    lo = *(uint32_t*)&L;
}

// ---------------------------------------------------------------------------
__global__ void init_kernel(float* __restrict__ out) {
    if (blockIdx.x == 0 && threadIdx.x < Em) g_cnt[threadIdx.x] = 0;
    const int gtid = blockIdx.x * blockDim.x + threadIdx.x;
    for (int i = gtid; i < MAXROWS; i += gridDim.x * blockDim.x) g_row_tok[i] = -1;
    float4 z = make_float4(0.f, 0.f, 0.f, 0.f);
    float4* o4 = (float4*)out;
    const int n4 = NTOK * Dm / 4;
    for (int i = gtid; i < n4; i += gridDim.x * blockDim.x) o4[i] = z;
}

// ---------------------------------------------------------------------------
__global__ void router_kernel(const float* __restrict__ x,
                              const int*   __restrict__ city_p,
                              const float* __restrict__ dt,
                              const float* __restrict__ dd,
                              const float* __restrict__ drg,
                              const float* __restrict__ de,
                              const float* __restrict__ cemb,
                              const float* __restrict__ Wr,
                              const float* __restrict__ br,
                              float* __restrict__ gate1) {
    const int warp = threadIdx.x >> 5;
    const int lane = threadIdx.x & 31;
    const int t = blockIdx.x * (blockDim.x >> 5) + warp;
    if (t >= NTOK) return;
    const int city = city_p[0];

    float acc[8];
#pragma unroll
    for (int e = 0; e < 8; e++) acc[e] = 0.f;

    for (int l = lane; l < LSm; l += 32) {
        float f;
        if      (l < 1024) f = x  [(size_t)t * 1024 + l];
        else if (l < 1056) f = cemb[city * 32 + (l - 1024)];
        else if (l < 1312) f = dt [(size_t)t * 256 + (l - 1056)];
        else if (l < 1568) f = dd [(size_t)t * 256 + (l - 1312)];
        else if (l < 1696) f = drg[(size_t)t * 128 + (l - 1568)];
        else               f = de [(size_t)t * 128 + (l - 1696)];
        const float4* w4 = (const float4*)(Wr + (size_t)l * 8);
        float4 w0 = w4[0], w1 = w4[1];
        acc[0] = fmaf(f, w0.x, acc[0]); acc[1] = fmaf(f, w0.y, acc[1]);
        acc[2] = fmaf(f, w0.z, acc[2]); acc[3] = fmaf(f, w0.w, acc[3]);
        acc[4] = fmaf(f, w1.x, acc[4]); acc[5] = fmaf(f, w1.y, acc[5]);
        acc[6] = fmaf(f, w1.z, acc[6]); acc[7] = fmaf(f, w1.w, acc[7]);
    }
#pragma unroll
    for (int e = 0; e < 8; e++)
#pragma unroll
        for (int o = 16; o > 0; o >>= 1)
            acc[e] += __shfl_xor_sync(0xffffffffu, acc[e], o);

    if (lane == 0) {
        float lg[8];
#pragma unroll
        for (int e = 0; e < 8; e++) lg[e] = acc[e] + br[e];
        float mx = lg[0];
#pragma unroll
        for (int e = 1; e < 8; e++) mx = fmaxf(mx, lg[e]);
        float ex[8], s = 0.f;
#pragma unroll
        for (int e = 0; e < 8; e++) { ex[e] = expf(lg[e] - mx); s += ex[e]; }
        const float inv = 1.f / s;
#pragma unroll
        for (int e = 0; e < 8; e++) gate1[(size_t)t * 8 + e] = ex[e] * inv;
        int i0 = 0; float v0 = lg[0];
#pragma unroll
        for (int e = 1; e < 8; e++) if (lg[e] > v0) { v0 = lg[e]; i0 = e; }
        int i1 = -1; float v1 = -1e30f;
#pragma unroll
        for (int e = 0; e < 8; e++)
            if (e != i0 && lg[e] > v1) { v1 = lg[e]; i1 = e; }
        const float e1 = expf(v1 - v0);
        const float g0 = 1.f / (1.f + e1);
        const float g1 = e1 / (1.f + e1);
        g_top_e[t * 2 + 0] = i0; g_top_g[t * 2 + 0] = g0;
        g_top_e[t * 2 + 1] = i1; g_top_g[t * 2 + 1] = g1;
        atomicAdd(&g_cnt[i0], 1);
        atomicAdd(&g_cnt[i1], 1);
    }
}

// ---------------------------------------------------------------------------
__global__ void offsets_kernel() {
    int total = 0;
    for (int e = 0; e < Em; e++) {
        g_off[e] = total;
        total += (g_cnt[e] + (MTILE - 1)) & ~(MTILE - 1);
        g_cursor[e] = 0;
    }
    g_off[Em] = total;
}

__global__ void build_kernel() {
    int t = blockIdx.x * blockDim.x + threadIdx.x;
    if (t >= NTOK) return;
#pragma unroll
    for (int j = 0; j < 2; j++) {
        int e = g_top_e[t * 2 + j];
        int pos = atomicAdd(&g_cursor[e], 1);
        int r = g_off[e] + pos;
        g_row_tok[r]  = t;
        g_row_gate[r] = g_top_g[t * 2 + j];
    }
}

__device__ __forceinline__ float gelu_tanh(float v) {
    float c = v * v * v;
    return 0.5f * v * (1.f + tanhf(0.7978845608028654f * (v + 0.044715f * c)));
}

// ---------------------------------------------------------------------------
// load + convert + store one BK chunk (A from rows, B from weights)
// ---------------------------------------------------------------------------
__device__ __forceinline__ void fill_slot_A(char* smem, int tid, int k0,
                                            const float* __restrict__ xbase,
                                            const int* toks, int KDIM) {
#pragma unroll
    for (int it = 0; it < 4; it++) {
        const int idx = tid + it * 256;
        const int r = idx >> 3, q = idx & 7;
        const int tok = toks[r];
        float4 v = (tok >= 0)
            ? *(const float4*)(xbase + (size_t)tok * KDIM + k0 + q * 4)
            : make_float4(0.f, 0.f, 0.f, 0.f);
        uint32_t h0, l0, h1, l1;
        split2(v.x, v.y, h0, l0);
        split2(v.z, v.w, h1, l1);
        *(uint2*)(smem + r * ROWB + q * 8) = make_uint2(h0, h1);
        *(uint2*)(smem + PLANE_BYTES + r * ROWB + q * 8) = make_uint2(l0, l1);
    }
}

__device__ __forceinline__ void fill_slot_A_dense(char* smem, int tid, int k0,
                                                  const float* __restrict__ rows,
                                                  int KDIM) {
#pragma unroll
    for (int it = 0; it < 4; it++) {
        const int idx = tid + it * 256;
        const int r = idx >> 3, q = idx & 7;
        float4 v = *(const float4*)(rows + (size_t)r * KDIM + k0 + q * 4);
        uint32_t h0, l0, h1, l1;
        split2(v.x, v.y, h0, l0);
        split2(v.z, v.w, h1, l1);
        *(uint2*)(smem + r * ROWB + q * 8) = make_uint2(h0, h1);
        *(uint2*)(smem + PLANE_BYTES + r * ROWB + q * 8) = make_uint2(l0, l1);
    }
}

__device__ __forceinline__ void fill_slot_B(char* smem, int tid, int k0,
                                            const float* __restrict__ W,
                                            int NDIM) {
#pragma unroll
    for (int u = 0; u < 2; u++) {
        const int idx = tid + u * 256;
        const int kp = idx >> 5, n4 = idx & 31;
        const float* bp_ = W + (size_t)(k0 + 2 * kp) * NDIM + 4 * n4;
        float4 f0 = *(const float4*)bp_;
        float4 f1 = *(const float4*)(bp_ + NDIM);
        const float* p0 = (const float*)&f0;
        const float* p1 = (const float*)&f1;
#pragma unroll
        for (int j = 0; j < 4; j++) {
            uint32_t h, l;
            split2(p0[j], p1[j], h, l);   // (k even, k odd) pair
            *(uint32_t*)(smem + 2 * PLANE_BYTES + (4 * n4 + j) * ROWB + kp * 4) = h;
            *(uint32_t*)(smem + 3 * PLANE_BYTES + (4 * n4 + j) * ROWB + kp * 4) = l;
        }
    }
}

__device__ __forceinline__ void mma_chunk(const char* smem, int wm, int wn,
                                          int gr, int tc, float (*cacc)[4][4]) {
    const uint32_t* Ah = (const uint32_t*)(smem);
    const uint32_t* Al = (const uint32_t*)(smem + PLANE_BYTES);
    const uint32_t* Bh = (const uint32_t*)(smem + 2 * PLANE_BYTES);
    const uint32_t* Bl = (const uint32_t*)(smem + 3 * PLANE_BYTES);
#pragma unroll
    for (int ks = 0; ks < 2; ks++) {
        const int kb = ks * 8;
        uint32_t bh[4][2], bl[4][2];
#pragma unroll
        for (int nt = 0; nt < 4; nt++) {
            const int n = wn * 32 + nt * 8 + gr;
            bh[nt][0] = Bh[n * 20 + kb + tc];
            bh[nt][1] = Bh[n * 20 + kb + 4 + tc];
            bl[nt][0] = Bl[n * 20 + kb + tc];
            bl[nt][1] = Bl[n * 20 + kb + 4 + tc];
        }
#pragma unroll
        for (int mt = 0; mt < 4; mt++) {
            const int r = wm * 64 + mt * 16 + gr;
            uint32_t ah[4], al[4];
            ah[0] = Ah[r * 20 + kb + tc];
            ah[1] = Ah[(r + 8) * 20 + kb + tc];
            ah[2] = Ah[r * 20 + kb + 4 + tc];
            ah[3] = Ah[(r + 8) * 20 + kb + 4 + tc];
            al[0] = Al[r * 20 + kb + tc];
            al[1] = Al[(r + 8) * 20 + kb + tc];
            al[2] = Al[r * 20 + kb + 4 + tc];
            al[3] = Al[(r + 8) * 20 + kb + 4 + tc];
#pragma unroll
            for (int nt = 0; nt < 4; nt++) {
                MMA16816(cacc[mt][nt], ah, bh[nt]);
                MMA16816(cacc[mt][nt], ah, bl[nt]);
                MMA16816(cacc[mt][nt], al, bh[nt]);
            }
        }
    }
}

// ---------------------------------------------------------------------------
// fc: h[r,:] = gelu(x[tok(r)] @ Wfc[e] + bfc[e])   (fp32 h output)
// grid: (m-tiles, n-tiles) — m fast for W L2 reuse
// ---------------------------------------------------------------------------
__global__ void __launch_bounds__(256, 2)
fc_mma(const float* __restrict__ x, const float* __restrict__ Wfc,
       const float* __restrict__ bfc) {
    const int row0 = blockIdx.x * MTILE;
    if (row0 >= g_off[Em]) return;
    int e = 0;
#pragma unroll
    for (int k = 1; k < Em; k++) if (g_off[k] <= row0) e = k;
    const int n0 = blockIdx.y * 128;

    __shared__ __align__(16) char smem[SLOT_BYTES];
    __shared__ int toks_sm[128];
    const int tid = threadIdx.x;
    const int wid = tid >> 5, lane = tid & 31;
    const int wm = wid & 1, wn = wid >> 1;
    const int gr = lane >> 2, tc = lane & 3;

    if (tid < 128) toks_sm[tid] = g_row_tok[row0 + tid];

    const float* We = Wfc + (size_t)e * Dm * Hm + n0;

    float cacc[4][4][4];
#pragma unroll
    for (int i = 0; i < 4; i++)
#pragma unroll
        for (int j = 0; j < 4; j++)
#pragma unroll
            for (int q = 0; q < 4; q++) cacc[i][j][q] = 0.f;

    __syncthreads();

    const int NC = Dm / BK;
    for (int cc = 0; cc < NC; cc++) {
        const int k0 = cc * BK;
        fill_slot_A(smem, tid, k0, x, toks_sm, Dm);
        fill_slot_B(smem, tid, k0, We, Hm);
        __syncthreads();
        mma_chunk(smem, wm, wn, gr, tc, cacc);
        __syncthreads();
    }

    const float* bptr = bfc + (size_t)e * Hm + n0 + wn * 32;
    const int rbase = row0 + wm * 64;
    const int csub = 2 * tc;
#pragma unroll
    for (int mt = 0; mt < 4; mt++) {
        const int r0 = rbase + mt * 16 + gr;
        const int r1 = r0 + 8;
#pragma unroll
        for (int nt = 0; nt < 4; nt++) {
            const int coll = wn * 32 + nt * 8 + csub;
            const float b0 = bptr[nt * 8 + csub];
            const float b1 = bptr[nt * 8 + csub + 1];
            float2 v0 = make_float2(gelu_tanh(cacc[mt][nt][0] + b0),
                                    gelu_tanh(cacc[mt][nt][1] + b1));
            float2 v1 = make_float2(gelu_tanh(cacc[mt][nt][2] + b0),
                                    gelu_tanh(cacc[mt][nt][3] + b1));
            *(float2*)(g_h + (size_t)r0 * Hm + n0 + coll) = v0;
            *(float2*)(g_h + (size_t)r1 * Hm + n0 + coll) = v1;
        }
    }
}

// ---------------------------------------------------------------------------
// proj: out[tok(r),:] += gate(r) * (h[r] @ Wproj[e] + bproj[e])
// ---------------------------------------------------------------------------
__global__ void __launch_bounds__(256, 2)
pj_mma(const float* __restrict__ Wp, const float* __restrict__ bp,
       float* __restrict__ out) {
    const int row0 = blockIdx.x * MTILE;
    if (row0 >= g_off[Em]) return;
    int e = 0;
#pragma unroll
    for (int k = 1; k < Em; k++) if (g_off[k] <= row0) e = k;
    const int n0 = blockIdx.y * 128;

    __shared__ __align__(16) char smem[SLOT_BYTES];
    const int tid = threadIdx.x;
    const int wid = tid >> 5, lane = tid & 31;
    const int wm = wid & 1, wn = wid >> 1;
    const int gr = lane >> 2, tc = lane & 3;

    const float* We = Wp + (size_t)e * Hm * Dm + n0;
    const float* hrows = g_h + (size_t)row0 * Hm;

    float cacc[4][4][4];
#pragma unroll
    for (int i = 0; i < 4; i++)
#pragma unroll
        for (int j = 0; j < 4; j++)
#pragma unroll
            for (int q = 0; q < 4; q++) cacc[i][j][q] = 0.f;

    const int NC = Hm / BK;
    for (int cc = 0; cc < NC; cc++) {
        const int k0 = cc * BK;
        fill_slot_A_dense(smem, tid, k0, hrows, Hm);
        fill_slot_B(smem, tid, k0, We, Dm);
        __syncthreads();
        mma_chunk(smem, wm, wn, gr, tc, cacc);
        __syncthreads();
    }

    const float* bptr = bp + (size_t)e * Dm + n0 + wn * 32;
    const int rbase = row0 + wm * 64;
    const int csub = 2 * tc;
#pragma unroll
    for (int mt = 0; mt < 4; mt++) {
        const int r0 = rbase + mt * 16 + gr;
        const int r1 = r0 + 8;
#pragma unroll
        for (int nt = 0; nt < 4; nt++) {
            const int coll = wn * 32 + nt * 8 + csub;
            const float b0 = bptr[nt * 8 + csub];
            const float b1 = bptr[nt * 8 + csub + 1];
            const int t0 = g_row_tok[r0];
            const int t1 = g_row_tok[r1];
            if (t0 >= 0) {
                const float g = g_row_gate[r0];
                float* op = out + (size_t)t0 * Dm + n0 + coll;
                atomicAdd(op,     g * (cacc[mt][nt][0] + b0));
                atomicAdd(op + 1, g * (cacc[mt][nt][1] + b1));
            }
            if (t1 >= 0) {
                const float g = g_row_gate[r1];
                float* op = out + (size_t)t1 * Dm + n0 + coll;
                atomicAdd(op,     g * (cacc[mt][nt][2] + b0));
                atomicAdd(op + 1, g * (cacc[mt][nt][3] + b1));
            }
        }
    }
}

// ---------------------------------------------------------------------------
extern "C" void kernel_launch(void* const* d_in, const int* in_sizes, int n_in,
                              void* d_out, int out_size) {
    const float* x    = (const float*)d_in[0];
    const int*   city = (const int*)  d_in[1];
    const float* dt   = (const float*)d_in[2];
    const float* dd   = (const float*)d_in[3];
    const float* drg  = (const float*)d_in[4];
    const float* de   = (const float*)d_in[5];
    const float* cemb = (const float*)d_in[6];
    const float* Wr   = (const float*)d_in[7];
    const float* br   = (const float*)d_in[8];
    const float* Wfc  = (const float*)d_in[9];
    const float* bfc  = (const float*)d_in[10];
    const float* Wp   = (const float*)d_in[11];
    const float* bp   = (const float*)d_in[12];

    float* out   = (float*)d_out;
    float* gate1 = out + (size_t)NTOK * Dm;

    init_kernel<<<2048, 256>>>(out);
    router_kernel<<<NTOK / 8, 256>>>(x, city, dt, dd, drg, de, cemb, Wr, br, gate1);
    offsets_kernel<<<1, 1>>>();
    build_kernel<<<NTOK / 256, 256>>>();
    fc_mma<<<dim3(MAXTILES, Hm / 128), 256>>>(x, Wfc, bfc);
    pj_mma<<<dim3(MAXTILES, Dm / 128), 256>>>(Wp, bp, out);
}

// round 12
// speedup vs baseline: 1.3782x; 1.3782x over previous
#include <cuda_runtime.h>
#include <cuda_bf16.h>
#include <stdint.h>
#include <math.h>

#define NTOK 16384
#define Dm   1024
#define Hm   4096
#define Em   8
#define LSm  1824
#define MTILE 128
#define NTILE 64
#define MAXROWS 33792        // 264 * 128
#define MAXTILES 264
#define BK 16                // bf16 K per chunk (32B data/row)
#define ROWB 48              // 32B data + 16B pad
#define A_PLANE (128 * ROWB)     // 6144
#define B_PLANE (64 * ROWB)      // 3072
#define SLOT_B  (2 * A_PLANE + 2 * B_PLANE)   // 18432
// static smem: 2 slots = 36864 B  (< 48KB static limit)

// ------- device scratch (554 MB, same as R8/R9 proven-safe) -------
__device__ int   g_cnt[Em];
__device__ int   g_off[Em + 1];
__device__ int   g_cursor[Em];
__device__ int   g_top_e[NTOK * 2];
__device__ float g_top_g[NTOK * 2];
__device__ int   g_row_tok[MAXROWS];
__device__ float g_row_gate[MAXROWS];
__device__ float g_h[(size_t)MAXROWS * Hm];   // fp32 hidden, 553 MB

#define MMA16816(d, a, b) \
    asm volatile("mma.sync.aligned.m16n8k16.row.col.f32.bf16.bf16.f32 " \
        "{%0,%1,%2,%3}, {%4,%5,%6,%7}, {%8,%9}, {%0,%1,%2,%3};" \
        : "+f"((d)[0]), "+f"((d)[1]), "+f"((d)[2]), "+f"((d)[3]) \
        : "r"((a)[0]), "r"((a)[1]), "r"((a)[2]), "r"((a)[3]), \
          "r"((b)[0]), "r"((b)[1]))
#define LDMX4(r, addr) \
    asm volatile("ldmatrix.sync.aligned.m8n8.x4.shared.b16 {%0,%1,%2,%3}, [%4];" \
        : "=r"((r)[0]), "=r"((r)[1]), "=r"((r)[2]), "=r"((r)[3]) : "r"(addr))
#define LDMX2(r, addr) \
    asm volatile("ldmatrix.sync.aligned.m8n8.x2.shared.b16 {%0,%1}, [%2];" \
        : "=r"((r)[0]), "=r"((r)[1]) : "r"(addr))

__device__ __forceinline__ void split2(float a, float b,
                                       uint32_t& hi, uint32_t& lo) {
    __nv_bfloat162 H = __float22bfloat162_rn(make_float2(a, b));
    uint32_t hbits = *(uint32_t*)&H;
    float ha_f = __uint_as_float(hbits << 16);
    float hb_f = __uint_as_float(hbits & 0xFFFF0000u);
    __nv_bfloat162 L = __float22bfloat162_rn(make_float2(a - ha_f, b - hb_f));
    hi = hbits;
    lo = *(uint32_t*)&L;
}

// ---------------------------------------------------------------------------
__global__ void init_kernel(float* __restrict__ out) {
    if (blockIdx.x == 0 && threadIdx.x < Em) g_cnt[threadIdx.x] = 0;
    const int gtid = blockIdx.x * blockDim.x + threadIdx.x;
    for (int i = gtid; i < MAXROWS; i += gridDim.x * blockDim.x) g_row_tok[i] = -1;
    float4 z = make_float4(0.f, 0.f, 0.f, 0.f);
    float4* o4 = (float4*)out;
    const int n4 = NTOK * Dm / 4;
    for (int i = gtid; i < n4; i += gridDim.x * blockDim.x) o4[i] = z;
}

// ---------------------------------------------------------------------------
__global__ void router_kernel(const float* __restrict__ x,
                              const int*   __restrict__ city_p,
                              const float* __restrict__ dt,
                              const float* __restrict__ dd,
                              const float* __restrict__ drg,
                              const float* __restrict__ de,
                              const float* __restrict__ cemb,
                              const float* __restrict__ Wr,
                              const float* __restrict__ br,
                              float* __restrict__ gate1) {
    const int warp = threadIdx.x >> 5;
    const int lane = threadIdx.x & 31;
    const int t = blockIdx.x * (blockDim.x >> 5) + warp;
    if (t >= NTOK) return;
    const int city = city_p[0];

    float acc[8];
#pragma unroll
    for (int e = 0; e < 8; e++) acc[e] = 0.f;

    for (int l = lane; l < LSm; l += 32) {
        float f;
        if      (l < 1024) f = x  [(size_t)t * 1024 + l];
        else if (l < 1056) f = cemb[city * 32 + (l - 1024)];
        else if (l < 1312) f = dt [(size_t)t * 256 + (l - 1056)];
        else if (l < 1568) f = dd [(size_t)t * 256 + (l - 1312)];
        else if (l < 1696) f = drg[(size_t)t * 128 + (l - 1568)];
        else               f = de [(size_t)t * 128 + (l - 1696)];
        const float4* w4 = (const float4*)(Wr + (size_t)l * 8);
        float4 w0 = w4[0], w1 = w4[1];
        acc[0] = fmaf(f, w0.x, acc[0]); acc[1] = fmaf(f, w0.y, acc[1]);
        acc[2] = fmaf(f, w0.z, acc[2]); acc[3] = fmaf(f, w0.w, acc[3]);
        acc[4] = fmaf(f, w1.x, acc[4]); acc[5] = fmaf(f, w1.y, acc[5]);
        acc[6] = fmaf(f, w1.z, acc[6]); acc[7] = fmaf(f, w1.w, acc[7]);
    }
#pragma unroll
    for (int e = 0; e < 8; e++)
#pragma unroll
        for (int o = 16; o > 0; o >>= 1)
            acc[e] += __shfl_xor_sync(0xffffffffu, acc[e], o);

    if (lane == 0) {
        float lg[8];
#pragma unroll
        for (int e = 0; e < 8; e++) lg[e] = acc[e] + br[e];
        float mx = lg[0];
#pragma unroll
        for (int e = 1; e < 8; e++) mx = fmaxf(mx, lg[e]);
        float ex[8], s = 0.f;
#pragma unroll
        for (int e = 0; e < 8; e++) { ex[e] = expf(lg[e] - mx); s += ex[e]; }
        const float inv = 1.f / s;
#pragma unroll
        for (int e = 0; e < 8; e++) gate1[(size_t)t * 8 + e] = ex[e] * inv;
        int i0 = 0; float v0 = lg[0];
#pragma unroll
        for (int e = 1; e < 8; e++) if (lg[e] > v0) { v0 = lg[e]; i0 = e; }
        int i1 = -1; float v1 = -1e30f;
#pragma unroll
        for (int e = 0; e < 8; e++)
            if (e != i0 && lg[e] > v1) { v1 = lg[e]; i1 = e; }
        const float e1 = expf(v1 - v0);
        const float g0 = 1.f / (1.f + e1);
        const float g1 = e1 / (1.f + e1);
        g_top_e[t * 2 + 0] = i0; g_top_g[t * 2 + 0] = g0;
        g_top_e[t * 2 + 1] = i1; g_top_g[t * 2 + 1] = g1;
        atomicAdd(&g_cnt[i0], 1);
        atomicAdd(&g_cnt[i1], 1);
    }
}

// ---------------------------------------------------------------------------
__global__ void offsets_kernel() {
    int total = 0;
    for (int e = 0; e < Em; e++) {
        g_off[e] = total;
        total += (g_cnt[e] + (MTILE - 1)) & ~(MTILE - 1);
        g_cursor[e] = 0;
    }
    g_off[Em] = total;
}

__global__ void build_kernel() {
    int t = blockIdx.x * blockDim.x + threadIdx.x;
    if (t >= NTOK) return;
#pragma unroll
    for (int j = 0; j < 2; j++) {
        int e = g_top_e[t * 2 + j];
        int pos = atomicAdd(&g_cursor[e], 1);
        int r = g_off[e] + pos;
        g_row_tok[r]  = t;
        g_row_gate[r] = g_top_g[t * 2 + j];
    }
}

// exact identity: 0.5*(1+tanh(z)) == sigmoid(2z); __expf err ~1e-7
__device__ __forceinline__ float gelu_f(float v) {
    float z2 = 1.5957691216057308f * (v + 0.044715f * v * v * v);
    return v / (1.f + __expf(-z2));
}

// ---------------------------------------------------------------------------
// STS helpers: convert prefetched fp32 regs -> hi/lo bf16 planes in smem slot
// ---------------------------------------------------------------------------
__device__ __forceinline__ void sts_A(char* slot, int tid, const float4* apf) {
#pragma unroll
    for (int it = 0; it < 2; it++) {
        const int idx = tid + it * 256;
        const int r = idx >> 2, q = idx & 3;
        uint32_t h0, l0, h1, l1;
        split2(apf[it].x, apf[it].y, h0, l0);
        split2(apf[it].z, apf[it].w, h1, l1);
        *(uint2*)(slot + r * ROWB + q * 8) = make_uint2(h0, h1);
        *(uint2*)(slot + A_PLANE + r * ROWB + q * 8) = make_uint2(l0, l1);
    }
}
__device__ __forceinline__ void sts_B(char* slot, int tid,
                                      float2 f0, float2 f1) {
    const int kp = tid >> 5, n2 = tid & 31;   // kp 0..7, n2 0..31 (2 n each)
    uint32_t h, l;
    split2(f0.x, f1.x, h, l);
    *(uint32_t*)(slot + 2 * A_PLANE + (2 * n2) * ROWB + kp * 4) = h;
    *(uint32_t*)(slot + 2 * A_PLANE + B_PLANE + (2 * n2) * ROWB + kp * 4) = l;
    split2(f0.y, f1.y, h, l);
    *(uint32_t*)(slot + 2 * A_PLANE + (2 * n2 + 1) * ROWB + kp * 4) = h;
    *(uint32_t*)(slot + 2 * A_PLANE + B_PLANE + (2 * n2 + 1) * ROWB + kp * 4) = l;
}

// ---------------------------------------------------------------------------
// per-chunk MMA via ldmatrix.  warp: rows wm*32, cols wn*32.
// ---------------------------------------------------------------------------
__device__ __forceinline__ void mma_chunk(uint32_t s32, int wm, int wn,
                                          int lane, float (*cacc)[4][4]) {
    const uint32_t a_l = (lane & 15) * ROWB + (lane >> 4) * 16;
    const uint32_t b_l = (lane & 7) * ROWB + ((lane >> 3) & 1) * 16;
    uint32_t bh[4][2], bl[4][2];
#pragma unroll
    for (int nt = 0; nt < 4; nt++) {
        uint32_t ad = s32 + 2 * A_PLANE + (wn * 32 + nt * 8) * ROWB + b_l;
        LDMX2(bh[nt], ad);
        LDMX2(bl[nt], ad + B_PLANE);
    }
#pragma unroll
    for (int mt = 0; mt < 2; mt++) {
        uint32_t ad = s32 + (wm * 32 + mt * 16) * ROWB + a_l;
        uint32_t ah[4], al[4];
        LDMX4(ah, ad);
        LDMX4(al, ad + A_PLANE);
#pragma unroll
        for (int nt = 0; nt < 4; nt++) {
            MMA16816(cacc[mt][nt], ah, bh[nt]);
            MMA16816(cacc[mt][nt], ah, bl[nt]);
            MMA16816(cacc[mt][nt], al, bh[nt]);
        }
    }
}

// ---------------------------------------------------------------------------
// fc: h[r,:] = gelu(x[tok(r)] @ Wfc[e] + bfc[e])   128x64 tile, BK=16
// ---------------------------------------------------------------------------
__global__ void __launch_bounds__(256, 2)
fc_mma(const float* __restrict__ x, const float* __restrict__ Wfc,
       const float* __restrict__ bfc) {
    const int row0 = blockIdx.y * MTILE;
    if (row0 >= g_off[Em]) return;
    int e = 0;
#pragma unroll
    for (int k = 1; k < Em; k++) if (g_off[k] <= row0) e = k;
    const int n0 = blockIdx.x * NTILE;

    __shared__ __align__(16) char smem[2 * SLOT_B];   // 36864 B
    __shared__ int toks_sm[128];
    const uint32_t s32 = (uint32_t)__cvta_generic_to_shared(smem);
    const int tid = threadIdx.x;
    const int wid = tid >> 5, lane = tid & 31;
    const int wm = wid & 3, wn = wid >> 2;
    const int gr = lane >> 2, tc = lane & 3;

    if (tid < 128) toks_sm[tid] = g_row_tok[row0 + tid];
    __syncthreads();

    const float* We = Wfc + (size_t)e * Dm * Hm + n0;
    const int pr = tid >> 2, pq = tid & 3;          // A prefetch row/quarter
    const int kp = tid >> 5, n2 = tid & 31;         // B prefetch

    float4 apf[2]; float2 bf0, bf1;
    auto prefetch = [&](int k0) {
#pragma unroll
        for (int it = 0; it < 2; it++) {
            const int r = pr + it * 64;
            const int tok = toks_sm[r];
            apf[it] = (tok >= 0)
                ? *(const float4*)(x + (size_t)tok * Dm + k0 + pq * 4)
                : make_float4(0.f, 0.f, 0.f, 0.f);
        }
        const float* wp = We + (size_t)(k0 + 2 * kp) * Hm + 2 * n2;
        bf0 = *(const float2*)wp;
        bf1 = *(const float2*)(wp + Hm);
    };

    float cacc[2][4][4];
#pragma unroll
    for (int i = 0; i < 2; i++)
#pragma unroll
        for (int j = 0; j < 4; j++)
#pragma unroll
            for (int q = 0; q < 4; q++) cacc[i][j][q] = 0.f;

    const int NC = Dm / BK;
    prefetch(0);
    sts_A(smem, tid, apf);
    sts_B(smem, tid, bf0, bf1);
    __syncthreads();

    for (int cc = 0; cc < NC; cc++) {
        if (cc + 1 < NC) prefetch((cc + 1) * BK);
        mma_chunk(s32 + (cc & 1) * SLOT_B, wm, wn, lane, cacc);
        if (cc + 1 < NC) {
            char* nslot = smem + ((cc + 1) & 1) * SLOT_B;
            sts_A(nslot, tid, apf);
            sts_B(nslot, tid, bf0, bf1);
        }
        __syncthreads();
    }

    const float* bptr = bfc + (size_t)e * Hm + n0 + wn * 32;
    const int rbase = row0 + wm * 32;
    const int csub = 2 * tc;
#pragma unroll
    for (int mt = 0; mt < 2; mt++) {
        const int r0 = rbase + mt * 16 + gr;
        const int r1 = r0 + 8;
#pragma unroll
        for (int nt = 0; nt < 4; nt++) {
            const int coll = wn * 32 + nt * 8 + csub;
            const float b0 = bptr[nt * 8 + csub];
            const float b1 = bptr[nt * 8 + csub + 1];
            float2 v0 = make_float2(gelu_f(cacc[mt][nt][0] + b0),
                                    gelu_f(cacc[mt][nt][1] + b1));
            float2 v1 = make_float2(gelu_f(cacc[mt][nt][2] + b0),
                                    gelu_f(cacc[mt][nt][3] + b1));
            *(float2*)(g_h + (size_t)r0 * Hm + n0 + coll) = v0;
            *(float2*)(g_h + (size_t)r1 * Hm + n0 + coll) = v1;
        }
    }
}

// ---------------------------------------------------------------------------
// pj: out[tok(r),:] += gate(r) * (h[r] @ Wproj[e] + bproj[e])  128x64, BK=16
// ---------------------------------------------------------------------------
__global__ void __launch_bounds__(256, 2)
pj_mma(const float* __restrict__ Wp, const float* __restrict__ bp,
       float* __restrict__ out) {
    const int row0 = blockIdx.y * MTILE;
    if (row0 >= g_off[Em]) return;
    int e = 0;
#pragma unroll
    for (int k = 1; k < Em; k++) if (g_off[k] <= row0) e = k;
    const int n0 = blockIdx.x * NTILE;

    __shared__ __align__(16) char smem[2 * SLOT_B];
    const uint32_t s32 = (uint32_t)__cvta_generic_to_shared(smem);
    const int tid = threadIdx.x;
    const int wid = tid >> 5, lane = tid & 31;
    const int wm = wid & 3, wn = wid >> 2;
    const int gr = lane >> 2, tc = lane & 3;

    const float* We = Wp + (size_t)e * Hm * Dm + n0;
    const float* hrows = g_h + (size_t)row0 * Hm;
    const int pr = tid >> 2, pq = tid & 3;
    const int kp = tid >> 5, n2 = tid & 31;

    float4 apf[2]; float2 bf0, bf1;
    auto prefetch = [&](int k0) {
#pragma unroll
        for (int it = 0; it < 2; it++) {
            const int r = pr + it * 64;
            apf[it] = *(const float4*)(hrows + (size_t)r * Hm + k0 + pq * 4);
        }
        const float* wp = We + (size_t)(k0 + 2 * kp) * Dm + 2 * n2;
        bf0 = *(const float2*)wp;
        bf1 = *(const float2*)(wp + Dm);
    };

    float cacc[2][4][4];
#pragma unroll
    for (int i = 0; i < 2; i++)
#pragma unroll
        for (int j = 0; j < 4; j++)
#pragma unroll
            for (int q = 0; q < 4; q++) cacc[i][j][q] = 0.f;

    const int NC = Hm / BK;
    prefetch(0);
    sts_A(smem, tid, apf);
    sts_B(smem, tid, bf0, bf1);
    __syncthreads();

    for (int cc = 0; cc < NC; cc++) {
        if (cc + 1 < NC) prefetch((cc + 1) * BK);
        mma_chunk(s32 + (cc & 1) * SLOT_B, wm, wn, lane, cacc);
        if (cc + 1 < NC) {
            char* nslot = smem + ((cc + 1) & 1) * SLOT_B;
            sts_A(nslot, tid, apf);
            sts_B(nslot, tid, bf0, bf1);
        }
        __syncthreads();
    }

    const float* bptr = bp + (size_t)e * Dm + n0 + wn * 32;
    const int rbase = row0 + wm * 32;
    const int csub = 2 * tc;
#pragma unroll
    for (int mt = 0; mt < 2; mt++) {
        const int r0 = rbase + mt * 16 + gr;
        const int r1 = r0 + 8;
#pragma unroll
        for (int nt = 0; nt < 4; nt++) {
            const int coll = wn * 32 + nt * 8 + csub;
            const float b0 = bptr[nt * 8 + csub];
            const float b1 = bptr[nt * 8 + csub + 1];
            const int t0 = g_row_tok[r0];
            const int t1 = g_row_tok[r1];
            if (t0 >= 0) {
                const float g = g_row_gate[r0];
                float* op = out + (size_t)t0 * Dm + n0 + coll;
                atomicAdd(op,     g * (cacc[mt][nt][0] + b0));
                atomicAdd(op + 1, g * (cacc[mt][nt][1] + b1));
            }
            if (t1 >= 0) {
                const float g = g_row_gate[r1];
                float* op = out + (size_t)t1 * Dm + n0 + coll;
                atomicAdd(op,     g * (cacc[mt][nt][2] + b0));
                atomicAdd(op + 1, g * (cacc[mt][nt][3] + b1));
            }
        }
    }
}

// ---------------------------------------------------------------------------
extern "C" void kernel_launch(void* const* d_in, const int* in_sizes, int n_in,
                              void* d_out, int out_size) {
    const float* x    = (const float*)d_in[0];
    const int*   city = (const int*)  d_in[1];
    const float* dt   = (const float*)d_in[2];
    const float* dd   = (const float*)d_in[3];
    const float* drg  = (const float*)d_in[4];
    const float* de   = (const float*)d_in[5];
    const float* cemb = (const float*)d_in[6];
    const float* Wr   = (const float*)d_in[7];
    const float* br   = (const float*)d_in[8];
    const float* Wfc  = (const float*)d_in[9];
    const float* bfc  = (const float*)d_in[10];
    const float* Wp   = (const float*)d_in[11];
    const float* bp   = (const float*)d_in[12];

    float* out   = (float*)d_out;
    float* gate1 = out + (size_t)NTOK * Dm;

    init_kernel<<<2048, 256>>>(out);
    router_kernel<<<NTOK / 8, 256>>>(x, city, dt, dd, drg, de, cemb, Wr, br, gate1);
    offsets_kernel<<<1, 1>>>();
    build_kernel<<<NTOK / 256, 256>>>();
    fc_mma<<<dim3(Hm / NTILE, MAXTILES), 256>>>(x, Wfc, bfc);
    pj_mma<<<dim3(Dm / NTILE, MAXTILES), 256>>>(Wp, bp, out);
}